// round 15
// baseline (speedup 1.0000x reference)
#include <cuda_runtime.h>
#include <cuda_fp16.h>
#include <cstdint>
#include <cstddef>

// ---------------- problem constants ----------------
#define N_TOT 16384      // B*H*W = 16*32*32
#define M_TOT 4096
#define KDIM  64
#define NTILES 128       // N_TOT / 128
#define MTILES 32        // M_TOT / 128

// ---------------- device scratch ----------------
__device__ __align__(16) __half g_zh[(size_t)N_TOT * KDIM];  // -2*z, [n][64]
__device__ __align__(16) __half g_eh[(size_t)M_TOT * KDIM];  // e,    [m][64]
__device__ float    g_zsq[N_TOT];
__device__ float    g_esq[M_TOT];
__device__ unsigned g_wmax[M_TOT];
__device__ float    g_t[M_TOT];
__device__ float    g_t2[M_TOT];
__device__ float    g_pmin[NTILES * M_TOT];   // per-(ntile,col) dmin (d2-space)
__device__ float    g_psum[NTILES * M_TOT];   // per-(ntile,col) window sums
__device__ float    g_lse[M_TOT];
__device__ int      g_flags[M_TOT];
__device__ int      g_flagcnt;
__device__ int      g_done;                   // last-block ticket

// ---------------- helpers ----------------
__device__ __forceinline__ uint32_t s2u(const void* p) {
    return (uint32_t)__cvta_generic_to_shared(p);
}

__device__ __forceinline__ void ldsm4(uint32_t& r0, uint32_t& r1, uint32_t& r2,
                                      uint32_t& r3, uint32_t addr) {
    asm volatile("ldmatrix.sync.aligned.m8n8.x4.shared.b16 {%0,%1,%2,%3}, [%4];"
                 : "=r"(r0), "=r"(r1), "=r"(r2), "=r"(r3) : "r"(addr));
}

__device__ __forceinline__ void mma_f16(float c[4], const uint32_t a[4],
                                        uint32_t b0, uint32_t b1) {
    asm volatile(
        "mma.sync.aligned.m16n8k16.row.col.f32.f16.f16.f32 "
        "{%0,%1,%2,%3}, {%4,%5,%6,%7}, {%8,%9}, {%0,%1,%2,%3};"
        : "+f"(c[0]), "+f"(c[1]), "+f"(c[2]), "+f"(c[3])
        : "r"(a[0]), "r"(a[1]), "r"(a[2]), "r"(a[3]), "r"(b0), "r"(b1));
}

__device__ __forceinline__ void cp_async16(uint32_t dst, const void* src) {
    asm volatile("cp.async.cg.shared.global [%0], [%1], 16;"
                 :: "r"(dst), "l"(src));
}
#define CP_COMMIT() asm volatile("cp.async.commit_group;" ::: "memory")
#define CP_WAIT1()  asm volatile("cp.async.wait_group 1;" ::: "memory")
#define CP_WAIT0()  asm volatile("cp.async.wait_group 0;" ::: "memory")

// p-generalized "above-branch" value function: v(d2) = d2^p  (p=2 -> d2*d2)
__device__ __forceinline__ float vfun(float d2, bool fast, float pf) {
    return fast ? d2 * d2 : __powf(d2, pf);
}

__device__ __forceinline__ void get_alpha_p(const float* lsig, const int* pptr,
                                            int has_p, float& alpha, float& pf,
                                            bool& fast) {
    float ls = lsig[0];
    alpha = -0.5f * __expf(-2.f * ls);   // < 0
    int praw = has_p ? *pptr : 2;
    pf = (praw > 0 && praw < 1000) ? (float)praw : __int_as_float(praw);
    fast = (pf == 2.0f);
}

// ---------------- kernel 1 (fused): z+e norms, half conversions, resets --------
__global__ void prep_all(const float* __restrict__ z, const float* __restrict__ e) {
    int i = blockIdx.x * 256 + threadIdx.x;        // grid covers N_TOT
    {   // z part: norms + (-2z) half conversion, coalesced over hw
        int b = i >> 10, hw = i & 1023;
        const float* zp = z + (size_t)b * 65536 + hw;
        float acc = 0.f;
        uint4* dst = (uint4*)(g_zh + (size_t)i * KDIM);
        #pragma unroll
        for (int k8 = 0; k8 < 8; k8++) {
            float v[8];
            #pragma unroll
            for (int q = 0; q < 8; q++) {
                v[q] = zp[(k8 * 8 + q) * 1024];
                acc += v[q] * v[q];
            }
            __half2 h0 = __floats2half2_rn(-2.f * v[0], -2.f * v[1]);
            __half2 h1 = __floats2half2_rn(-2.f * v[2], -2.f * v[3]);
            __half2 h2 = __floats2half2_rn(-2.f * v[4], -2.f * v[5]);
            __half2 h3 = __floats2half2_rn(-2.f * v[6], -2.f * v[7]);
            dst[k8] = make_uint4(*(uint32_t*)&h0, *(uint32_t*)&h1,
                                 *(uint32_t*)&h2, *(uint32_t*)&h3);
        }
        g_zsq[i] = acc;
    }
    if (i < M_TOT) {   // e part: norms + half conversion + resets
        const float4* p = (const float4*)(e + (size_t)i * KDIM);
        float acc = 0.f;
        uint4* dst = (uint4*)(g_eh + (size_t)i * KDIM);
        #pragma unroll
        for (int k8 = 0; k8 < 8; k8++) {
            float4 va = p[k8 * 2], vb = p[k8 * 2 + 1];
            acc += va.x * va.x + va.y * va.y + va.z * va.z + va.w * va.w
                 + vb.x * vb.x + vb.y * vb.y + vb.z * vb.z + vb.w * vb.w;
            __half2 h0 = __floats2half2_rn(va.x, va.y);
            __half2 h1 = __floats2half2_rn(va.z, va.w);
            __half2 h2 = __floats2half2_rn(vb.x, vb.y);
            __half2 h3 = __floats2half2_rn(vb.z, vb.w);
            dst[k8] = make_uint4(*(uint32_t*)&h0, *(uint32_t*)&h1,
                                 *(uint32_t*)&h2, *(uint32_t*)&h3);
        }
        g_esq[i] = acc;
        g_wmax[i] = 0u;
        if (i == 0) { g_flagcnt = 0; g_done = 0; }
    }
}

// ---------------- kernel 2: fused fp16 GEMM + wmax + lse partials ----------------
// Tile 128(n) x 128(m), 512 threads (16 warps), warp tile 64x16, K=64 in 4 k16
// steps, 2 CTAs/SM -> 32 warps/SM. A/B via cp.async group 1 (gates MMAs),
// belong 128x128 f32 tile via group 2 (gates epilogue). belong pitch 136 floats
// -> conflict-free LDS.64. Two-pass epilogue: pass A = branch-free d2-min + wmax;
// pass B = rare-window exp. A holds -2*z so d2 = zsq + esq + acc.
#define HPITCH_B 144                         // bytes per half-tile row (A/B)
#define BELP 136                             // belong smem pitch in floats
#define SM_A    0                            // 128*144 = 18432
#define SM_B    18432                        // 128*144 = 18432
#define SM_ZSQ  36864                        // 512
#define SM_ESQ  37376                        // 512
#define SM_MRG  37888                        // 3 * 1024 = 3072 -> 40960
#define SM_BEL  40960                        // 128*136*4 = 69632
#define SMEM_BYTES (40960 + 128 * BELP * 4)  // 110592 (x2 CTAs = 221184)

__global__ __launch_bounds__(512, 2) void gemm_fused(const float* __restrict__ z,
                                                     const float* __restrict__ e,
                                                     const float* __restrict__ belong,
                                                     const float* __restrict__ lsig,
                                                     const int* __restrict__ pptr,
                                                     int has_p) {
    extern __shared__ __align__(16) unsigned char smraw[];
    const uint32_t smb = s2u(smraw);

    const int tid = threadIdx.x;
    const int m0 = blockIdx.x * 128;
    const int n0 = blockIdx.y * 128;
    const int ntile = blockIdx.y;
    const int lane = tid & 31, wid = tid >> 5;

    float alpha, pf; bool fast;
    get_alpha_p(lsig, pptr, has_p, alpha, pf, fast);
    const float margin = -30.f / alpha;                // v-space contribution cutoff

    // ---- group 1: stage A/B via cp.async from pre-converted halves ----
    {
        const __half* zsrc = g_zh + (size_t)n0 * KDIM;
        #pragma unroll
        for (int it = 0; it < 2; it++) {
            int idx = tid + it * 512;                  // 0..1023, 8 chunks/row
            int row = idx >> 3, c = idx & 7;
            cp_async16(smb + SM_A + row * HPITCH_B + c * 16,
                       zsrc + row * KDIM + c * 8);
        }
        const __half* esrc = g_eh + (size_t)m0 * KDIM;
        #pragma unroll
        for (int it = 0; it < 2; it++) {
            int idx = tid + it * 512;                  // 0..1023
            int row = idx >> 3, c = idx & 7;
            cp_async16(smb + SM_B + row * HPITCH_B + c * 16,
                       esrc + row * KDIM + c * 8);
        }
        CP_COMMIT();
    }
    // ---- group 2: belong tile [128 x 128] f32, coalesced, pitch 136 ----
    {
        const float* bsrc = belong + (size_t)n0 * M_TOT + m0;
        #pragma unroll
        for (int it = 0; it < 8; it++) {
            int idx = tid + it * 512;                  // 0..4095 16B-chunks
            int row = idx >> 5, c16 = idx & 31;        // 32 chunks per 128-f row
            cp_async16(smb + SM_BEL + row * (BELP * 4) + c16 * 16,
                       bsrc + (size_t)row * M_TOT + c16 * 4);
        }
        CP_COMMIT();
    }

    float* szsq = (float*)(smraw + SM_ZSQ);
    float* sesq = (float*)(smraw + SM_ESQ);
    if (tid < 128) szsq[tid] = g_zsq[n0 + tid];
    else if (tid < 256) sesq[tid - 128] = g_esq[m0 + tid - 128];
    CP_WAIT1();                 // A/B landed (belong may still be in flight)
    __syncthreads();

    const int wm = wid >> 3;       // 0..1 (n halves, 64 rows each)
    const int wn = wid & 7;        // 0..7 (m eighths, 16 cols each)
    const int ar = lane >> 2, ac = lane & 3;

    // ldmatrix lane addressing
    const uint32_t a_base = smb + SM_A +
        (uint32_t)((wm * 64 + (lane & 7) + ((lane >> 3) & 1) * 8) * HPITCH_B) +
        ((lane >> 4) & 1) * 16;
    const uint32_t b_base = smb + SM_B +
        (uint32_t)((wn * 16 + (lane & 7) + ((lane >> 3) & 1) * 8) * HPITCH_B) +
        ((lane >> 4) & 1) * 16;

    // =================== MMAs: warp tile 64x16, acc[4][2][4] ===================
    float acc[4][2][4];
    #pragma unroll
    for (int i = 0; i < 4; i++)
        #pragma unroll
        for (int j = 0; j < 2; j++)
            #pragma unroll
            for (int r = 0; r < 4; r++) acc[i][j][r] = 0.f;

    #pragma unroll
    for (int ks = 0; ks < 4; ks++) {
        uint32_t a[4][4], b[2][2];
        #pragma unroll
        for (int i = 0; i < 4; i++)
            ldsm4(a[i][0], a[i][1], a[i][2], a[i][3],
                  a_base + i * 16 * HPITCH_B + ks * 32);
        ldsm4(b[0][0], b[1][0], b[0][1], b[1][1], b_base + ks * 32);
        #pragma unroll
        for (int i = 0; i < 4; i++)
            #pragma unroll
            for (int j = 0; j < 2; j++)
                mma_f16(acc[i][j], a[i], b[j][0], b[j][1]);
    }

    float zsv[4][2];
    #pragma unroll
    for (int i = 0; i < 4; i++) {
        int lr0 = wm * 64 + i * 16 + ar;
        zsv[i][0] = szsq[lr0];
        zsv[i][1] = szsq[lr0 + 8];
    }
    float esv[2][2];
    #pragma unroll
    for (int j = 0; j < 2; j++) {
        int lc = wn * 16 + j * 8 + 2 * ac;
        esv[j][0] = sesq[lc];
        esv[j][1] = sesq[lc + 1];
    }

    // belong must have landed + be visible across threads
    CP_WAIT0();
    __syncthreads();
    const float* sbel = (const float*)(smraw + SM_BEL);

    // =================== pass A: branch-free min(d2) + max(b^2*d2) ==============
    float dmin_[2][2], wloc[2][2];
    #pragma unroll
    for (int j = 0; j < 2; j++)
        #pragma unroll
        for (int p_ = 0; p_ < 2; p_++) { dmin_[j][p_] = 1e19f; wloc[j][p_] = 0.f; }

    const int lc0 = wn * 16 + 2 * ac;      // local belong col base
    #pragma unroll
    for (int i = 0; i < 4; i++) {
        int lr0 = wm * 64 + i * 16 + ar;
        float zs0 = zsv[i][0], zs1 = zsv[i][1];
        float2 b00 = *(const float2*)(sbel + lr0 * BELP + lc0);
        float2 b10 = *(const float2*)(sbel + (lr0 + 8) * BELP + lc0);
        float2 b01 = *(const float2*)(sbel + lr0 * BELP + lc0 + 8);
        float2 b11 = *(const float2*)(sbel + (lr0 + 8) * BELP + lc0 + 8);
        #pragma unroll
        for (int j = 0; j < 2; j++) {
            float es0 = esv[j][0], es1 = esv[j][1];
            float d00 = (zs0 + es0) + acc[i][j][0];
            float d01 = (zs0 + es1) + acc[i][j][1];
            float d10 = (zs1 + es0) + acc[i][j][2];
            float d11 = (zs1 + es1) + acc[i][j][3];
            float2 b0 = (j == 0) ? b00 : b01;
            float2 b1 = (j == 0) ? b10 : b11;
            wloc[j][0] = fmaxf(wloc[j][0], fmaxf(b0.x * b0.x * d00, b1.x * b1.x * d10));
            wloc[j][1] = fmaxf(wloc[j][1], fmaxf(b0.y * b0.y * d01, b1.y * b1.y * d11));
            dmin_[j][0] = fminf(dmin_[j][0], fminf(d00, d10));
            dmin_[j][1] = fminf(dmin_[j][1], fminf(d01, d11));
        }
    }

    // butterfly min/max over ar-lanes -> column-uniform dm, wmax
    float dm_[2][2], vm_[2][2], dthr_[2][2];
    #pragma unroll
    for (int j = 0; j < 2; j++)
        #pragma unroll
        for (int p_ = 0; p_ < 2; p_++) {
            float dm = dmin_[j][p_];
            #pragma unroll
            for (int off = 4; off < 32; off <<= 1)
                dm = fminf(dm, __shfl_xor_sync(0xffffffffu, dm, off));
            float wv = wloc[j][p_];
            #pragma unroll
            for (int off = 4; off < 32; off <<= 1)
                wv = fmaxf(wv, __shfl_xor_sync(0xffffffffu, wv, off));
            wloc[j][p_] = wv;
            dm_[j][p_] = dm;
            float vm = vfun(dm, fast, pf);
            vm_[j][p_] = vm;
            float vlim = vm + margin;
            dthr_[j][p_] = fast ? sqrtf(fmaxf(vlim, 0.f)) : __powf(vlim, 1.f / pf);
        }

    // =================== pass B: rare-window exp sums ===========================
    float s_[2][2] = {{0.f, 0.f}, {0.f, 0.f}};
    #pragma unroll
    for (int i = 0; i < 4; i++) {
        float zs0 = zsv[i][0], zs1 = zsv[i][1];
        #pragma unroll
        for (int j = 0; j < 2; j++) {
            float es0 = esv[j][0], es1 = esv[j][1];
            float dv[4];
            dv[0] = (zs0 + es0) + acc[i][j][0];
            dv[1] = (zs0 + es1) + acc[i][j][1];
            dv[2] = (zs1 + es0) + acc[i][j][2];
            dv[3] = (zs1 + es1) + acc[i][j][3];
            #pragma unroll
            for (int r = 0; r < 4; r++) {
                int p_ = r & 1;
                float d2 = dv[r];
                if (__builtin_expect(d2 < dthr_[j][p_], 0))
                    s_[j][p_] += __expf(alpha * (vfun(d2, fast, pf) - vm_[j][p_]));
            }
        }
    }

    float* sMD = (float*)(smraw + SM_MRG);
    float* sMS = sMD + 256;
    float* sMW = sMD + 512;
    #pragma unroll
    for (int j = 0; j < 2; j++)
        #pragma unroll
        for (int p_ = 0; p_ < 2; p_++) {
            float sv = s_[j][p_];
            #pragma unroll
            for (int off = 4; off < 32; off <<= 1)
                sv += __shfl_xor_sync(0xffffffffu, sv, off);
            if (lane < 4) {
                int col = wn * 16 + j * 8 + 2 * lane + p_;
                sMD[wm * 128 + col] = dm_[j][p_];
                sMS[wm * 128 + col] = sv;
                sMW[wm * 128 + col] = wloc[j][p_];
            }
        }
    __syncthreads();

    if (tid < 128) {
        int col = tid;
        float d0 = sMD[col], d1 = sMD[128 + col];
        float dm = fminf(d0, d1);
        float vm = vfun(dm, fast, pf);
        float s = sMS[col] * __expf(alpha * (vfun(d0, fast, pf) - vm))
                + sMS[128 + col] * __expf(alpha * (vfun(d1, fast, pf) - vm));
        g_pmin[ntile * M_TOT + m0 + col] = dm;
        g_psum[ntile * M_TOT + m0 + col] = s;
        atomicMax(&g_wmax[m0 + col],
                  __float_as_uint(fmaxf(sMW[col], sMW[128 + col])));
    }
}

// ---------------- kernel 3 (fused tail): newmax + lse + fixup + loss ----------
// grid 128 blocks x 256 threads. Each block: EMA newmax + combine 128 tiles ->
// lse + flag for its 32 columns. The LAST block (atomic ticket) then exactly
// recomputes flagged columns (rare; usually zero) and reduces lse -> loss.
__global__ void finalize_fused(const float* __restrict__ maxd,
                               const float* __restrict__ lsig,
                               const int* __restrict__ pptr, int has_p,
                               const float* __restrict__ z,
                               const float* __restrict__ e,
                               float* __restrict__ out) {
    __shared__ float s_t2[32];
    __shared__ float sdm[8][32];
    __shared__ float ssm[8][32];
    __shared__ int   s_last;
    const int lane = threadIdx.x & 31;
    const int warp = threadIdx.x >> 5;
    const int tid = threadIdx.x;
    const int col = blockIdx.x * 32 + lane;

    float alpha, pf; bool fast;
    get_alpha_p(lsig, pptr, has_p, alpha, pf, fast);

    if (tid < 32) {   // EMA new_max for this block's 32 columns
        float bm = sqrtf(__uint_as_float(g_wmax[col]));
        float nm = fmaxf(0.999f * maxd[col] + 0.001f * bm, 1e-8f);
        g_t[col] = nm;
        g_t2[col] = nm * nm;
        s_t2[lane] = nm * nm;
    }

    float dmc = 3.0e38f, s = 0.f;
    #pragma unroll 4
    for (int t = warp * 16; t < warp * 16 + 16; t++) {
        float pm = g_pmin[t * M_TOT + col];
        float ps = g_psum[t * M_TOT + col];
        if (pm < dmc) {
            s = s * __expf(alpha * (vfun(dmc, fast, pf) - vfun(pm, fast, pf))) + ps;
            dmc = pm;
        } else {
            s += ps * __expf(alpha * (vfun(pm, fast, pf) - vfun(dmc, fast, pf)));
        }
    }
    sdm[warp][lane] = dmc;
    ssm[warp][lane] = s;
    __syncthreads();

    if (warp == 0) {
        float dall = 3.0e38f;
        #pragma unroll
        for (int w = 0; w < 8; w++) dall = fminf(dall, sdm[w][lane]);
        float vall = vfun(dall, fast, pf);
        float sall = 0.f;
        #pragma unroll
        for (int w = 0; w < 8; w++)
            sall += ssm[w][lane] * __expf(alpha * (vfun(sdm[w][lane], fast, pf) - vall));
        g_lse[col] = alpha * vall + logf(sall);
        if (dall < s_t2[lane]) {         // some element takes the below branch
            int idx = atomicAdd(&g_flagcnt, 1);
            g_flags[idx] = col;
        }
    }

    // ---- last-block ticket (threadFenceReduction pattern) ----
    __threadfence();                     // each thread publishes its writes
    __syncthreads();
    if (tid == 0) {
        int t = atomicAdd(&g_done, 1);
        s_last = (t == gridDim.x - 1);
    }
    __syncthreads();
    if (!s_last) return;
    __threadfence();                     // acquire: other blocks' lse/t/flags

    // ---- fixup: exact recompute for flagged columns (usually none) ----
    {
        __shared__ float esm[64];
        __shared__ float red_v[256];
        __shared__ float red_s[256];
        const int cnt = g_flagcnt;
        const float elo = 2.f / pf, ehi = 2.f * pf;
        for (int f = 0; f < cnt; f++) {
            int fcol = g_flags[f];
            if (tid < 64) esm[tid] = e[fcol * 64 + tid];
            __syncthreads();
            float t = g_t[fcol];
            float esq = g_esq[fcol];
            float vmin = 3.0e38f, sx = 0.f;
            for (int n = tid; n < N_TOT; n += 256) {
                const float* zp = z + (size_t)(n >> 10) * 65536 + (n & 1023);
                float dot = 0.f;
                #pragma unroll
                for (int k = 0; k < 64; k++) dot += zp[k * 1024] * esm[k];
                float d2 = fmaxf(g_zsq[n] + esq - 2.f * dot, 0.f);
                float dist = sqrtf(d2);
                float v;
                if (fast) v = (dist < t) ? dist : d2 * d2;
                else      v = (dist < t) ? __powf(dist, elo) : __powf(dist, ehi);
                if (v < vmin) {
                    sx = sx * __expf(alpha * (vmin - v)) + 1.f;
                    vmin = v;
                } else {
                    float a1 = alpha * (v - vmin);
                    if (a1 > -30.f) sx += __expf(a1);
                }
            }
            red_v[tid] = vmin; red_s[tid] = sx;
            __syncthreads();
            if (tid == 0) {
                float vm = 3.0e38f;
                for (int i = 0; i < 256; i++) vm = fminf(vm, red_v[i]);
                float ss = 0.f;
                for (int i = 0; i < 256; i++)
                    ss += red_s[i] * __expf(alpha * (red_v[i] - vm));
                g_lse[fcol] = alpha * vm + logf(ss);
            }
            __syncthreads();
        }
    }

    // ---- final reduction: loss = -mean(lse) + z_dim * log_sigma ----
    {
        __shared__ double red[256];
        double a = 0.0;
        for (int i = tid; i < M_TOT; i += 256) a += (double)g_lse[i];
        red[tid] = a;
        __syncthreads();
        for (int st = 128; st > 0; st >>= 1) {
            if (tid < st) red[tid] += red[tid + st];
            __syncthreads();
        }
        if (tid == 0) {
            double ls = (double)lsig[0];
            out[0] = (float)(-(red[0] / (double)M_TOT) + (double)KDIM * ls);
        }
    }
}

// ---------------- launch ----------------
extern "C" void kernel_launch(void* const* d_in, const int* in_sizes, int n_in,
                              void* d_out, int out_size) {
    const float* z      = (const float*)d_in[0];
    const float* e      = (const float*)d_in[1];
    const float* belong = (const float*)d_in[2];
    const float* lsig   = (const float*)d_in[3];
    const float* maxd   = (const float*)d_in[4];
    const int*   pptr   = (n_in > 5) ? (const int*)d_in[5] : nullptr;
    (void)in_sizes; (void)out_size;
    int has_p = pptr ? 1 : 0;

    cudaFuncSetAttribute(gemm_fused, cudaFuncAttributeMaxDynamicSharedMemorySize,
                         SMEM_BYTES);   // host-side API, idempotent (R10-proven)

    prep_all<<<N_TOT / 256, 256>>>(z, e);            // launch 1 (fused prep)
    gemm_fused<<<dim3(MTILES, NTILES), 512, SMEM_BYTES>>>(z, e, belong, lsig,
                                                          pptr, has_p);  // launch 2
    finalize_fused<<<M_TOT / 32, 256>>>(maxd, lsig, pptr, has_p,
                                        z, e, (float*)d_out);            // launch 3
}

// round 16
// speedup vs baseline: 1.0134x; 1.0134x over previous
#include <cuda_runtime.h>
#include <cuda_fp16.h>
#include <cstdint>
#include <cstddef>

// ---------------- problem constants ----------------
#define N_TOT 16384      // B*H*W = 16*32*32
#define M_TOT 4096
#define KDIM  64
#define NTILES 128       // N_TOT / 128
#define MTILES 32        // M_TOT / 128

// ---------------- device scratch ----------------
__device__ __align__(16) __half g_zh[(size_t)N_TOT * KDIM];  // -2*z, [n][64]
__device__ __align__(16) __half g_eh[(size_t)M_TOT * KDIM];  // e,    [m][64]
__device__ float    g_zsq[N_TOT];
__device__ float    g_esq[M_TOT];
__device__ unsigned g_wmax[M_TOT];
__device__ float    g_t[M_TOT];
__device__ float    g_t2[M_TOT];
__device__ float    g_pmin[NTILES * M_TOT];   // per-(ntile,col) dmin (d2-space)
__device__ float    g_psum[NTILES * M_TOT];   // per-(ntile,col) window sums
__device__ float    g_lse[M_TOT];
__device__ int      g_flags[M_TOT];
__device__ int      g_flagcnt;
__device__ int      g_done;                   // last-block ticket

// ---------------- helpers ----------------
__device__ __forceinline__ uint32_t s2u(const void* p) {
    return (uint32_t)__cvta_generic_to_shared(p);
}

__device__ __forceinline__ void ldsm4(uint32_t& r0, uint32_t& r1, uint32_t& r2,
                                      uint32_t& r3, uint32_t addr) {
    asm volatile("ldmatrix.sync.aligned.m8n8.x4.shared.b16 {%0,%1,%2,%3}, [%4];"
                 : "=r"(r0), "=r"(r1), "=r"(r2), "=r"(r3) : "r"(addr));
}

__device__ __forceinline__ void mma_f16(float c[4], const uint32_t a[4],
                                        uint32_t b0, uint32_t b1) {
    asm volatile(
        "mma.sync.aligned.m16n8k16.row.col.f32.f16.f16.f32 "
        "{%0,%1,%2,%3}, {%4,%5,%6,%7}, {%8,%9}, {%0,%1,%2,%3};"
        : "+f"(c[0]), "+f"(c[1]), "+f"(c[2]), "+f"(c[3])
        : "r"(a[0]), "r"(a[1]), "r"(a[2]), "r"(a[3]), "r"(b0), "r"(b1));
}

__device__ __forceinline__ void cp_async16(uint32_t dst, const void* src) {
    asm volatile("cp.async.cg.shared.global [%0], [%1], 16;"
                 :: "r"(dst), "l"(src));
}
#define CP_COMMIT() asm volatile("cp.async.commit_group;" ::: "memory")
#define CP_WAIT1()  asm volatile("cp.async.wait_group 1;" ::: "memory")
#define CP_WAIT0()  asm volatile("cp.async.wait_group 0;" ::: "memory")

// p-generalized "above-branch" value function: v(d2) = d2^p  (p=2 -> d2*d2)
__device__ __forceinline__ float vfun(float d2, bool fast, float pf) {
    return fast ? d2 * d2 : __powf(d2, pf);
}

__device__ __forceinline__ void get_alpha_p(const float* lsig, const int* pptr,
                                            int has_p, float& alpha, float& pf,
                                            bool& fast) {
    float ls = lsig[0];
    alpha = -0.5f * __expf(-2.f * ls);   // < 0
    int praw = has_p ? *pptr : 2;
    pf = (praw > 0 && praw < 1000) ? (float)praw : __int_as_float(praw);
    fast = (pf == 2.0f);
}

// ---------------- kernel 1 (fused): z+e norms, half conversions, resets --------
// 256 blocks x 256 threads. Each block: 64 z-rows, 4 threads per row (16 k each,
// coalesced over hw); partial norms combined via smem. Blocks 0-15 also handle
// the e rows + resets (1 MB; one thread per row as before).
__global__ void prep_all(const float* __restrict__ z, const float* __restrict__ e) {
    __shared__ float sacc[4][64];
    const int tid = threadIdx.x;
    const int rq = tid & 63;             // row within block
    const int kq = tid >> 6;             // 0..3: k-quarter
    const int n = blockIdx.x * 64 + rq;
    {
        int b = n >> 10, hw = n & 1023;
        const float* zp = z + (size_t)b * 65536 + hw + (size_t)(kq * 16) * 1024;
        float acc = 0.f;
        uint4* dst = (uint4*)(g_zh + (size_t)n * KDIM + kq * 16);
        #pragma unroll
        for (int k8 = 0; k8 < 2; k8++) {
            float v[8];
            #pragma unroll
            for (int q = 0; q < 8; q++) {
                v[q] = zp[(k8 * 8 + q) * 1024];
                acc += v[q] * v[q];
            }
            __half2 h0 = __floats2half2_rn(-2.f * v[0], -2.f * v[1]);
            __half2 h1 = __floats2half2_rn(-2.f * v[2], -2.f * v[3]);
            __half2 h2 = __floats2half2_rn(-2.f * v[4], -2.f * v[5]);
            __half2 h3 = __floats2half2_rn(-2.f * v[6], -2.f * v[7]);
            dst[k8] = make_uint4(*(uint32_t*)&h0, *(uint32_t*)&h1,
                                 *(uint32_t*)&h2, *(uint32_t*)&h3);
        }
        sacc[kq][rq] = acc;
    }
    __syncthreads();
    if (kq == 0)
        g_zsq[n] = (sacc[0][rq] + sacc[1][rq]) + (sacc[2][rq] + sacc[3][rq]);

    if (blockIdx.x < 16) {   // e part: norms + half conversion + resets
        int i = blockIdx.x * 256 + tid;  // covers M_TOT
        const float4* p = (const float4*)(e + (size_t)i * KDIM);
        float acc = 0.f;
        uint4* dst = (uint4*)(g_eh + (size_t)i * KDIM);
        #pragma unroll
        for (int k8 = 0; k8 < 8; k8++) {
            float4 va = p[k8 * 2], vb = p[k8 * 2 + 1];
            acc += va.x * va.x + va.y * va.y + va.z * va.z + va.w * va.w
                 + vb.x * vb.x + vb.y * vb.y + vb.z * vb.z + vb.w * vb.w;
            __half2 h0 = __floats2half2_rn(va.x, va.y);
            __half2 h1 = __floats2half2_rn(va.z, va.w);
            __half2 h2 = __floats2half2_rn(vb.x, vb.y);
            __half2 h3 = __floats2half2_rn(vb.z, vb.w);
            dst[k8] = make_uint4(*(uint32_t*)&h0, *(uint32_t*)&h1,
                                 *(uint32_t*)&h2, *(uint32_t*)&h3);
        }
        g_esq[i] = acc;
        g_wmax[i] = 0u;
        if (i == 0) { g_flagcnt = 0; g_done = 0; }
    }
}

// ---------------- kernel 2: fused fp16 GEMM + wmax + lse partials ----------------
// Tile 128(n) x 128(m), 512 threads (16 warps), warp tile 64x16, K=64 in 4 k16
// steps, 2 CTAs/SM -> 32 warps/SM. A/B via cp.async group 1 (gates MMAs),
// belong 128x128 f32 tile via group 2 (gates epilogue). belong pitch 136 floats
// -> conflict-free LDS.64. Two-pass epilogue: pass A = branch-free d2-min + wmax;
// pass B = rare-window exp. A holds -2*z so d2 = zsq + esq + acc.
#define HPITCH_B 144                         // bytes per half-tile row (A/B)
#define BELP 136                             // belong smem pitch in floats
#define SM_A    0                            // 128*144 = 18432
#define SM_B    18432                        // 128*144 = 18432
#define SM_ZSQ  36864                        // 512
#define SM_ESQ  37376                        // 512
#define SM_MRG  37888                        // 3 * 1024 = 3072 -> 40960
#define SM_BEL  40960                        // 128*136*4 = 69632
#define SMEM_BYTES (40960 + 128 * BELP * 4)  // 110592 (x2 CTAs = 221184)

__global__ __launch_bounds__(512, 2) void gemm_fused(const float* __restrict__ z,
                                                     const float* __restrict__ e,
                                                     const float* __restrict__ belong,
                                                     const float* __restrict__ lsig,
                                                     const int* __restrict__ pptr,
                                                     int has_p) {
    extern __shared__ __align__(16) unsigned char smraw[];
    const uint32_t smb = s2u(smraw);

    const int tid = threadIdx.x;
    const int m0 = blockIdx.x * 128;
    const int n0 = blockIdx.y * 128;
    const int ntile = blockIdx.y;
    const int lane = tid & 31, wid = tid >> 5;

    float alpha, pf; bool fast;
    get_alpha_p(lsig, pptr, has_p, alpha, pf, fast);
    const float margin = -30.f / alpha;                // v-space contribution cutoff

    // ---- group 1: stage A/B via cp.async from pre-converted halves ----
    {
        const __half* zsrc = g_zh + (size_t)n0 * KDIM;
        #pragma unroll
        for (int it = 0; it < 2; it++) {
            int idx = tid + it * 512;                  // 0..1023, 8 chunks/row
            int row = idx >> 3, c = idx & 7;
            cp_async16(smb + SM_A + row * HPITCH_B + c * 16,
                       zsrc + row * KDIM + c * 8);
        }
        const __half* esrc = g_eh + (size_t)m0 * KDIM;
        #pragma unroll
        for (int it = 0; it < 2; it++) {
            int idx = tid + it * 512;                  // 0..1023
            int row = idx >> 3, c = idx & 7;
            cp_async16(smb + SM_B + row * HPITCH_B + c * 16,
                       esrc + row * KDIM + c * 8);
        }
        CP_COMMIT();
    }
    // ---- group 2: belong tile [128 x 128] f32, coalesced, pitch 136 ----
    {
        const float* bsrc = belong + (size_t)n0 * M_TOT + m0;
        #pragma unroll
        for (int it = 0; it < 8; it++) {
            int idx = tid + it * 512;                  // 0..4095 16B-chunks
            int row = idx >> 5, c16 = idx & 31;        // 32 chunks per 128-f row
            cp_async16(smb + SM_BEL + row * (BELP * 4) + c16 * 16,
                       bsrc + (size_t)row * M_TOT + c16 * 4);
        }
        CP_COMMIT();
    }

    float* szsq = (float*)(smraw + SM_ZSQ);
    float* sesq = (float*)(smraw + SM_ESQ);
    if (tid < 128) szsq[tid] = g_zsq[n0 + tid];
    else if (tid < 256) sesq[tid - 128] = g_esq[m0 + tid - 128];
    CP_WAIT1();                 // A/B landed (belong may still be in flight)
    __syncthreads();

    const int wm = wid >> 3;       // 0..1 (n halves, 64 rows each)
    const int wn = wid & 7;        // 0..7 (m eighths, 16 cols each)
    const int ar = lane >> 2, ac = lane & 3;

    // ldmatrix lane addressing
    const uint32_t a_base = smb + SM_A +
        (uint32_t)((wm * 64 + (lane & 7) + ((lane >> 3) & 1) * 8) * HPITCH_B) +
        ((lane >> 4) & 1) * 16;
    const uint32_t b_base = smb + SM_B +
        (uint32_t)((wn * 16 + (lane & 7) + ((lane >> 3) & 1) * 8) * HPITCH_B) +
        ((lane >> 4) & 1) * 16;

    // =================== MMAs: warp tile 64x16, acc[4][2][4] ===================
    float acc[4][2][4];
    #pragma unroll
    for (int i = 0; i < 4; i++)
        #pragma unroll
        for (int j = 0; j < 2; j++)
            #pragma unroll
            for (int r = 0; r < 4; r++) acc[i][j][r] = 0.f;

    #pragma unroll
    for (int ks = 0; ks < 4; ks++) {
        uint32_t a[4][4], b[2][2];
        #pragma unroll
        for (int i = 0; i < 4; i++)
            ldsm4(a[i][0], a[i][1], a[i][2], a[i][3],
                  a_base + i * 16 * HPITCH_B + ks * 32);
        ldsm4(b[0][0], b[1][0], b[0][1], b[1][1], b_base + ks * 32);
        #pragma unroll
        for (int i = 0; i < 4; i++)
            #pragma unroll
            for (int j = 0; j < 2; j++)
                mma_f16(acc[i][j], a[i], b[j][0], b[j][1]);
    }

    float zsv[4][2];
    #pragma unroll
    for (int i = 0; i < 4; i++) {
        int lr0 = wm * 64 + i * 16 + ar;
        zsv[i][0] = szsq[lr0];
        zsv[i][1] = szsq[lr0 + 8];
    }
    float esv[2][2];
    #pragma unroll
    for (int j = 0; j < 2; j++) {
        int lc = wn * 16 + j * 8 + 2 * ac;
        esv[j][0] = sesq[lc];
        esv[j][1] = sesq[lc + 1];
    }

    // belong must have landed + be visible across threads
    CP_WAIT0();
    __syncthreads();
    const float* sbel = (const float*)(smraw + SM_BEL);

    // =================== pass A: branch-free min(d2) + max(b^2*d2) ==============
    float dmin_[2][2], wloc[2][2];
    #pragma unroll
    for (int j = 0; j < 2; j++)
        #pragma unroll
        for (int p_ = 0; p_ < 2; p_++) { dmin_[j][p_] = 1e19f; wloc[j][p_] = 0.f; }

    const int lc0 = wn * 16 + 2 * ac;      // local belong col base
    #pragma unroll
    for (int i = 0; i < 4; i++) {
        int lr0 = wm * 64 + i * 16 + ar;
        float zs0 = zsv[i][0], zs1 = zsv[i][1];
        float2 b00 = *(const float2*)(sbel + lr0 * BELP + lc0);
        float2 b10 = *(const float2*)(sbel + (lr0 + 8) * BELP + lc0);
        float2 b01 = *(const float2*)(sbel + lr0 * BELP + lc0 + 8);
        float2 b11 = *(const float2*)(sbel + (lr0 + 8) * BELP + lc0 + 8);
        #pragma unroll
        for (int j = 0; j < 2; j++) {
            float es0 = esv[j][0], es1 = esv[j][1];
            float d00 = (zs0 + es0) + acc[i][j][0];
            float d01 = (zs0 + es1) + acc[i][j][1];
            float d10 = (zs1 + es0) + acc[i][j][2];
            float d11 = (zs1 + es1) + acc[i][j][3];
            float2 b0 = (j == 0) ? b00 : b01;
            float2 b1 = (j == 0) ? b10 : b11;
            wloc[j][0] = fmaxf(wloc[j][0], fmaxf(b0.x * b0.x * d00, b1.x * b1.x * d10));
            wloc[j][1] = fmaxf(wloc[j][1], fmaxf(b0.y * b0.y * d01, b1.y * b1.y * d11));
            dmin_[j][0] = fminf(dmin_[j][0], fminf(d00, d10));
            dmin_[j][1] = fminf(dmin_[j][1], fminf(d01, d11));
        }
    }

    // butterfly min/max over ar-lanes -> column-uniform dm, wmax
    float dm_[2][2], vm_[2][2], dthr_[2][2];
    #pragma unroll
    for (int j = 0; j < 2; j++)
        #pragma unroll
        for (int p_ = 0; p_ < 2; p_++) {
            float dm = dmin_[j][p_];
            #pragma unroll
            for (int off = 4; off < 32; off <<= 1)
                dm = fminf(dm, __shfl_xor_sync(0xffffffffu, dm, off));
            float wv = wloc[j][p_];
            #pragma unroll
            for (int off = 4; off < 32; off <<= 1)
                wv = fmaxf(wv, __shfl_xor_sync(0xffffffffu, wv, off));
            wloc[j][p_] = wv;
            dm_[j][p_] = dm;
            float vm = vfun(dm, fast, pf);
            vm_[j][p_] = vm;
            float vlim = vm + margin;
            dthr_[j][p_] = fast ? sqrtf(fmaxf(vlim, 0.f)) : __powf(vlim, 1.f / pf);
        }

    // =================== pass B: rare-window exp sums ===========================
    float s_[2][2] = {{0.f, 0.f}, {0.f, 0.f}};
    #pragma unroll
    for (int i = 0; i < 4; i++) {
        float zs0 = zsv[i][0], zs1 = zsv[i][1];
        #pragma unroll
        for (int j = 0; j < 2; j++) {
            float es0 = esv[j][0], es1 = esv[j][1];
            float dv[4];
            dv[0] = (zs0 + es0) + acc[i][j][0];
            dv[1] = (zs0 + es1) + acc[i][j][1];
            dv[2] = (zs1 + es0) + acc[i][j][2];
            dv[3] = (zs1 + es1) + acc[i][j][3];
            #pragma unroll
            for (int r = 0; r < 4; r++) {
                int p_ = r & 1;
                float d2 = dv[r];
                if (__builtin_expect(d2 < dthr_[j][p_], 0))
                    s_[j][p_] += __expf(alpha * (vfun(d2, fast, pf) - vm_[j][p_]));
            }
        }
    }

    float* sMD = (float*)(smraw + SM_MRG);
    float* sMS = sMD + 256;
    float* sMW = sMD + 512;
    #pragma unroll
    for (int j = 0; j < 2; j++)
        #pragma unroll
        for (int p_ = 0; p_ < 2; p_++) {
            float sv = s_[j][p_];
            #pragma unroll
            for (int off = 4; off < 32; off <<= 1)
                sv += __shfl_xor_sync(0xffffffffu, sv, off);
            if (lane < 4) {
                int col = wn * 16 + j * 8 + 2 * lane + p_;
                sMD[wm * 128 + col] = dm_[j][p_];
                sMS[wm * 128 + col] = sv;
                sMW[wm * 128 + col] = wloc[j][p_];
            }
        }
    __syncthreads();

    if (tid < 128) {
        int col = tid;
        float d0 = sMD[col], d1 = sMD[128 + col];
        float dm = fminf(d0, d1);
        float vm = vfun(dm, fast, pf);
        float s = sMS[col] * __expf(alpha * (vfun(d0, fast, pf) - vm))
                + sMS[128 + col] * __expf(alpha * (vfun(d1, fast, pf) - vm));
        g_pmin[ntile * M_TOT + m0 + col] = dm;
        g_psum[ntile * M_TOT + m0 + col] = s;
        atomicMax(&g_wmax[m0 + col],
                  __float_as_uint(fmaxf(sMW[col], sMW[128 + col])));
    }
}

// ---------------- kernel 3 (fused tail): newmax + lse + fixup + loss ----------
// grid 128 blocks x 256 threads. Each block: EMA newmax + combine 128 tiles ->
// lse + flag for its 32 columns. The LAST block (atomic ticket) then exactly
// recomputes flagged columns (rare; usually zero) and reduces lse -> loss.
__global__ void finalize_fused(const float* __restrict__ maxd,
                               const float* __restrict__ lsig,
                               const int* __restrict__ pptr, int has_p,
                               const float* __restrict__ z,
                               const float* __restrict__ e,
                               float* __restrict__ out) {
    __shared__ float s_t2[32];
    __shared__ float sdm[8][32];
    __shared__ float ssm[8][32];
    __shared__ int   s_last;
    const int lane = threadIdx.x & 31;
    const int warp = threadIdx.x >> 5;
    const int tid = threadIdx.x;
    const int col = blockIdx.x * 32 + lane;

    float alpha, pf; bool fast;
    get_alpha_p(lsig, pptr, has_p, alpha, pf, fast);

    if (tid < 32) {   // EMA new_max for this block's 32 columns
        float bm = sqrtf(__uint_as_float(g_wmax[col]));
        float nm = fmaxf(0.999f * maxd[col] + 0.001f * bm, 1e-8f);
        g_t[col] = nm;
        g_t2[col] = nm * nm;
        s_t2[lane] = nm * nm;
    }

    float dmc = 3.0e38f, s = 0.f;
    #pragma unroll 4
    for (int t = warp * 16; t < warp * 16 + 16; t++) {
        float pm = g_pmin[t * M_TOT + col];
        float ps = g_psum[t * M_TOT + col];
        if (pm < dmc) {
            s = s * __expf(alpha * (vfun(dmc, fast, pf) - vfun(pm, fast, pf))) + ps;
            dmc = pm;
        } else {
            s += ps * __expf(alpha * (vfun(pm, fast, pf) - vfun(dmc, fast, pf)));
        }
    }
    sdm[warp][lane] = dmc;
    ssm[warp][lane] = s;
    __syncthreads();

    if (warp == 0) {
        float dall = 3.0e38f;
        #pragma unroll
        for (int w = 0; w < 8; w++) dall = fminf(dall, sdm[w][lane]);
        float vall = vfun(dall, fast, pf);
        float sall = 0.f;
        #pragma unroll
        for (int w = 0; w < 8; w++)
            sall += ssm[w][lane] * __expf(alpha * (vfun(sdm[w][lane], fast, pf) - vall));
        g_lse[col] = alpha * vall + logf(sall);
        if (dall < s_t2[lane]) {         // some element takes the below branch
            int idx = atomicAdd(&g_flagcnt, 1);
            g_flags[idx] = col;
        }
    }

    // ---- last-block ticket (threadFenceReduction pattern) ----
    __threadfence();                     // each thread publishes its writes
    __syncthreads();
    if (tid == 0) {
        int t = atomicAdd(&g_done, 1);
        s_last = (t == gridDim.x - 1);
    }
    __syncthreads();
    if (!s_last) return;
    __threadfence();                     // acquire: other blocks' lse/t/flags

    // ---- fixup: exact recompute for flagged columns (usually none) ----
    {
        __shared__ float esm[64];
        __shared__ float red_v[256];
        __shared__ float red_s[256];
        const int cnt = g_flagcnt;
        const float elo = 2.f / pf, ehi = 2.f * pf;
        for (int f = 0; f < cnt; f++) {
            int fcol = g_flags[f];
            if (tid < 64) esm[tid] = e[fcol * 64 + tid];
            __syncthreads();
            float t = g_t[fcol];
            float esq = g_esq[fcol];
            float vmin = 3.0e38f, sx = 0.f;
            for (int n = tid; n < N_TOT; n += 256) {
                const float* zp = z + (size_t)(n >> 10) * 65536 + (n & 1023);
                float dot = 0.f;
                #pragma unroll
                for (int k = 0; k < 64; k++) dot += zp[k * 1024] * esm[k];
                float d2 = fmaxf(g_zsq[n] + esq - 2.f * dot, 0.f);
                float dist = sqrtf(d2);
                float v;
                if (fast) v = (dist < t) ? dist : d2 * d2;
                else      v = (dist < t) ? __powf(dist, elo) : __powf(dist, ehi);
                if (v < vmin) {
                    sx = sx * __expf(alpha * (vmin - v)) + 1.f;
                    vmin = v;
                } else {
                    float a1 = alpha * (v - vmin);
                    if (a1 > -30.f) sx += __expf(a1);
                }
            }
            red_v[tid] = vmin; red_s[tid] = sx;
            __syncthreads();
            if (tid == 0) {
                float vm = 3.0e38f;
                for (int i = 0; i < 256; i++) vm = fminf(vm, red_v[i]);
                float ss = 0.f;
                for (int i = 0; i < 256; i++)
                    ss += red_s[i] * __expf(alpha * (red_v[i] - vm));
                g_lse[fcol] = alpha * vm + logf(ss);
            }
            __syncthreads();
        }
    }

    // ---- final reduction: loss = -mean(lse) + z_dim * log_sigma ----
    {
        __shared__ double red[256];
        double a = 0.0;
        for (int i = tid; i < M_TOT; i += 256) a += (double)g_lse[i];
        red[tid] = a;
        __syncthreads();
        for (int st = 128; st > 0; st >>= 1) {
            if (tid < st) red[tid] += red[tid + st];
            __syncthreads();
        }
        if (tid == 0) {
            double ls = (double)lsig[0];
            out[0] = (float)(-(red[0] / (double)M_TOT) + (double)KDIM * ls);
        }
    }
}

// ---------------- launch ----------------
extern "C" void kernel_launch(void* const* d_in, const int* in_sizes, int n_in,
                              void* d_out, int out_size) {
    const float* z      = (const float*)d_in[0];
    const float* e      = (const float*)d_in[1];
    const float* belong = (const float*)d_in[2];
    const float* lsig   = (const float*)d_in[3];
    const float* maxd   = (const float*)d_in[4];
    const int*   pptr   = (n_in > 5) ? (const int*)d_in[5] : nullptr;
    (void)in_sizes; (void)out_size;
    int has_p = pptr ? 1 : 0;

    cudaFuncSetAttribute(gemm_fused, cudaFuncAttributeMaxDynamicSharedMemorySize,
                         SMEM_BYTES);   // host-side API, idempotent (R10-proven)

    prep_all<<<N_TOT / 64, 256>>>(z, e);             // launch 1 (4x parallel prep)
    gemm_fused<<<dim3(MTILES, NTILES), 512, SMEM_BYTES>>>(z, e, belong, lsig,
                                                          pptr, has_p);  // launch 2
    finalize_fused<<<M_TOT / 32, 256>>>(maxd, lsig, pptr, has_p,
                                        z, e, (float*)d_out);            // launch 3
}

// round 17
// speedup vs baseline: 1.0170x; 1.0036x over previous
#include <cuda_runtime.h>
#include <cuda_fp16.h>
#include <cstdint>
#include <cstddef>

// ---------------- problem constants ----------------
#define N_TOT 16384      // B*H*W = 16*32*32
#define M_TOT 4096
#define KDIM  64
#define NTILES 128       // N_TOT / 128
#define MTILES 32        // M_TOT / 128

// ---------------- device scratch ----------------
__device__ __align__(16) __half g_zh[(size_t)N_TOT * KDIM];  // -2*z, [n][64]
__device__ __align__(16) __half g_eh[(size_t)M_TOT * KDIM];  // e,    [m][64]
__device__ float    g_zsq[N_TOT];
__device__ float    g_esq[M_TOT];
__device__ unsigned g_wmax[M_TOT];
__device__ float    g_t[M_TOT];
__device__ float    g_t2[M_TOT];
__device__ float    g_pmin[NTILES * M_TOT];   // per-(ntile,col) dmin (d2-space)
__device__ float    g_psum[NTILES * M_TOT];   // per-(ntile,col) window sums
__device__ float    g_lse[M_TOT];
__device__ int      g_flags[M_TOT];
__device__ int      g_flagcnt;
__device__ int      g_done;                   // last-block ticket

// ---------------- helpers ----------------
__device__ __forceinline__ uint32_t s2u(const void* p) {
    return (uint32_t)__cvta_generic_to_shared(p);
}

__device__ __forceinline__ void ldsm4(uint32_t& r0, uint32_t& r1, uint32_t& r2,
                                      uint32_t& r3, uint32_t addr) {
    asm volatile("ldmatrix.sync.aligned.m8n8.x4.shared.b16 {%0,%1,%2,%3}, [%4];"
                 : "=r"(r0), "=r"(r1), "=r"(r2), "=r"(r3) : "r"(addr));
}

__device__ __forceinline__ void mma_f16(float c[4], const uint32_t a[4],
                                        uint32_t b0, uint32_t b1) {
    asm volatile(
        "mma.sync.aligned.m16n8k16.row.col.f32.f16.f16.f32 "
        "{%0,%1,%2,%3}, {%4,%5,%6,%7}, {%8,%9}, {%0,%1,%2,%3};"
        : "+f"(c[0]), "+f"(c[1]), "+f"(c[2]), "+f"(c[3])
        : "r"(a[0]), "r"(a[1]), "r"(a[2]), "r"(a[3]), "r"(b0), "r"(b1));
}

__device__ __forceinline__ void cp_async16(uint32_t dst, const void* src) {
    asm volatile("cp.async.cg.shared.global [%0], [%1], 16;"
                 :: "r"(dst), "l"(src));
}
#define CP_COMMIT() asm volatile("cp.async.commit_group;" ::: "memory")
#define CP_WAIT1()  asm volatile("cp.async.wait_group 1;" ::: "memory")
#define CP_WAIT0()  asm volatile("cp.async.wait_group 0;" ::: "memory")

// p-generalized "above-branch" value function: v(d2) = d2^p  (p=2 -> d2*d2)
__device__ __forceinline__ float vfun(float d2, bool fast, float pf) {
    return fast ? d2 * d2 : __powf(d2, pf);
}

__device__ __forceinline__ void get_alpha_p(const float* lsig, const int* pptr,
                                            int has_p, float& alpha, float& pf,
                                            bool& fast) {
    float ls = lsig[0];
    alpha = -0.5f * __expf(-2.f * ls);   // < 0
    int praw = has_p ? *pptr : 2;
    pf = (praw > 0 && praw < 1000) ? (float)praw : __int_as_float(praw);
    fast = (pf == 2.0f);
}

// ---------------- kernel 1 (fused): z+e norms, half conversions, resets --------
// 512 blocks x 256 threads. Each block: 32 z-rows, 8 threads per row (8 k each,
// one uint4 store per thread, coalesced over hw); partial norms via smem.
// Blocks 0-15 also handle the e rows + resets.
__global__ void prep_all(const float* __restrict__ z, const float* __restrict__ e) {
    __shared__ float sacc[8][32];
    const int tid = threadIdx.x;
    const int rq = tid & 31;             // row within block
    const int kq = tid >> 5;             // 0..7: k-eighth
    const int n = blockIdx.x * 32 + rq;
    {
        int b = n >> 10, hw = n & 1023;
        const float* zp = z + (size_t)b * 65536 + hw + (size_t)(kq * 8) * 1024;
        float v[8];
        float acc = 0.f;
        #pragma unroll
        for (int q = 0; q < 8; q++) {
            v[q] = zp[q * 1024];
            acc += v[q] * v[q];
        }
        __half2 h0 = __floats2half2_rn(-2.f * v[0], -2.f * v[1]);
        __half2 h1 = __floats2half2_rn(-2.f * v[2], -2.f * v[3]);
        __half2 h2 = __floats2half2_rn(-2.f * v[4], -2.f * v[5]);
        __half2 h3 = __floats2half2_rn(-2.f * v[6], -2.f * v[7]);
        *(uint4*)(g_zh + (size_t)n * KDIM + kq * 8) =
            make_uint4(*(uint32_t*)&h0, *(uint32_t*)&h1,
                       *(uint32_t*)&h2, *(uint32_t*)&h3);
        sacc[kq][rq] = acc;
    }
    __syncthreads();
    if (kq == 0) {
        float a0 = sacc[0][rq] + sacc[1][rq];
        float a1 = sacc[2][rq] + sacc[3][rq];
        float a2 = sacc[4][rq] + sacc[5][rq];
        float a3 = sacc[6][rq] + sacc[7][rq];
        g_zsq[n] = (a0 + a1) + (a2 + a3);
    }

    if (blockIdx.x < 16) {   // e part: norms + half conversion + resets
        int i = blockIdx.x * 256 + tid;  // covers M_TOT
        const float4* p = (const float4*)(e + (size_t)i * KDIM);
        float acc = 0.f;
        uint4* dst = (uint4*)(g_eh + (size_t)i * KDIM);
        #pragma unroll
        for (int k8 = 0; k8 < 8; k8++) {
            float4 va = p[k8 * 2], vb = p[k8 * 2 + 1];
            acc += va.x * va.x + va.y * va.y + va.z * va.z + va.w * va.w
                 + vb.x * vb.x + vb.y * vb.y + vb.z * vb.z + vb.w * vb.w;
            __half2 h0 = __floats2half2_rn(va.x, va.y);
            __half2 h1 = __floats2half2_rn(va.z, va.w);
            __half2 h2 = __floats2half2_rn(vb.x, vb.y);
            __half2 h3 = __floats2half2_rn(vb.z, vb.w);
            dst[k8] = make_uint4(*(uint32_t*)&h0, *(uint32_t*)&h1,
                                 *(uint32_t*)&h2, *(uint32_t*)&h3);
        }
        g_esq[i] = acc;
        g_wmax[i] = 0u;
        if (i == 0) { g_flagcnt = 0; g_done = 0; }
    }
}

// ---------------- kernel 2: fused fp16 GEMM + wmax + lse partials ----------------
// Tile 128(n) x 128(m), 512 threads (16 warps), warp tile 64x16, K=64 in 4 k16
// steps, 2 CTAs/SM -> 32 warps/SM. A/B via cp.async group 1 (gates MMAs),
// belong 128x128 f32 tile via group 2 (gates epilogue). belong pitch 136 floats
// -> conflict-free LDS.64. Two-pass epilogue: pass A = branch-free d2-min + wmax;
// pass B = rare-window exp. A holds -2*z so d2 = zsq + esq + acc.
#define HPITCH_B 144                         // bytes per half-tile row (A/B)
#define BELP 136                             // belong smem pitch in floats
#define SM_A    0                            // 128*144 = 18432
#define SM_B    18432                        // 128*144 = 18432
#define SM_ZSQ  36864                        // 512
#define SM_ESQ  37376                        // 512
#define SM_MRG  37888                        // 3 * 1024 = 3072 -> 40960
#define SM_BEL  40960                        // 128*136*4 = 69632
#define SMEM_BYTES (40960 + 128 * BELP * 4)  // 110592 (x2 CTAs = 221184)

__global__ __launch_bounds__(512, 2) void gemm_fused(const float* __restrict__ z,
                                                     const float* __restrict__ e,
                                                     const float* __restrict__ belong,
                                                     const float* __restrict__ lsig,
                                                     const int* __restrict__ pptr,
                                                     int has_p) {
    extern __shared__ __align__(16) unsigned char smraw[];
    const uint32_t smb = s2u(smraw);

    const int tid = threadIdx.x;
    const int m0 = blockIdx.x * 128;
    const int n0 = blockIdx.y * 128;
    const int ntile = blockIdx.y;
    const int lane = tid & 31, wid = tid >> 5;

    float alpha, pf; bool fast;
    get_alpha_p(lsig, pptr, has_p, alpha, pf, fast);
    const float margin = -30.f / alpha;                // v-space contribution cutoff

    // ---- group 1: stage A/B via cp.async from pre-converted halves ----
    {
        const __half* zsrc = g_zh + (size_t)n0 * KDIM;
        #pragma unroll
        for (int it = 0; it < 2; it++) {
            int idx = tid + it * 512;                  // 0..1023, 8 chunks/row
            int row = idx >> 3, c = idx & 7;
            cp_async16(smb + SM_A + row * HPITCH_B + c * 16,
                       zsrc + row * KDIM + c * 8);
        }
        const __half* esrc = g_eh + (size_t)m0 * KDIM;
        #pragma unroll
        for (int it = 0; it < 2; it++) {
            int idx = tid + it * 512;                  // 0..1023
            int row = idx >> 3, c = idx & 7;
            cp_async16(smb + SM_B + row * HPITCH_B + c * 16,
                       esrc + row * KDIM + c * 8);
        }
        CP_COMMIT();
    }
    // ---- group 2: belong tile [128 x 128] f32, coalesced, pitch 136 ----
    {
        const float* bsrc = belong + (size_t)n0 * M_TOT + m0;
        #pragma unroll
        for (int it = 0; it < 8; it++) {
            int idx = tid + it * 512;                  // 0..4095 16B-chunks
            int row = idx >> 5, c16 = idx & 31;        // 32 chunks per 128-f row
            cp_async16(smb + SM_BEL + row * (BELP * 4) + c16 * 16,
                       bsrc + (size_t)row * M_TOT + c16 * 4);
        }
        CP_COMMIT();
    }

    float* szsq = (float*)(smraw + SM_ZSQ);
    float* sesq = (float*)(smraw + SM_ESQ);
    if (tid < 128) szsq[tid] = g_zsq[n0 + tid];
    else if (tid < 256) sesq[tid - 128] = g_esq[m0 + tid - 128];
    CP_WAIT1();                 // A/B landed (belong may still be in flight)
    __syncthreads();

    const int wm = wid >> 3;       // 0..1 (n halves, 64 rows each)
    const int wn = wid & 7;        // 0..7 (m eighths, 16 cols each)
    const int ar = lane >> 2, ac = lane & 3;

    // ldmatrix lane addressing
    const uint32_t a_base = smb + SM_A +
        (uint32_t)((wm * 64 + (lane & 7) + ((lane >> 3) & 1) * 8) * HPITCH_B) +
        ((lane >> 4) & 1) * 16;
    const uint32_t b_base = smb + SM_B +
        (uint32_t)((wn * 16 + (lane & 7) + ((lane >> 3) & 1) * 8) * HPITCH_B) +
        ((lane >> 4) & 1) * 16;

    // =================== MMAs: warp tile 64x16, acc[4][2][4] ===================
    float acc[4][2][4];
    #pragma unroll
    for (int i = 0; i < 4; i++)
        #pragma unroll
        for (int j = 0; j < 2; j++)
            #pragma unroll
            for (int r = 0; r < 4; r++) acc[i][j][r] = 0.f;

    #pragma unroll
    for (int ks = 0; ks < 4; ks++) {
        uint32_t a[4][4], b[2][2];
        #pragma unroll
        for (int i = 0; i < 4; i++)
            ldsm4(a[i][0], a[i][1], a[i][2], a[i][3],
                  a_base + i * 16 * HPITCH_B + ks * 32);
        ldsm4(b[0][0], b[1][0], b[0][1], b[1][1], b_base + ks * 32);
        #pragma unroll
        for (int i = 0; i < 4; i++)
            #pragma unroll
            for (int j = 0; j < 2; j++)
                mma_f16(acc[i][j], a[i], b[j][0], b[j][1]);
    }

    float zsv[4][2];
    #pragma unroll
    for (int i = 0; i < 4; i++) {
        int lr0 = wm * 64 + i * 16 + ar;
        zsv[i][0] = szsq[lr0];
        zsv[i][1] = szsq[lr0 + 8];
    }
    float esv[2][2];
    #pragma unroll
    for (int j = 0; j < 2; j++) {
        int lc = wn * 16 + j * 8 + 2 * ac;
        esv[j][0] = sesq[lc];
        esv[j][1] = sesq[lc + 1];
    }

    // belong must have landed + be visible across threads
    CP_WAIT0();
    __syncthreads();
    const float* sbel = (const float*)(smraw + SM_BEL);

    // =================== pass A: branch-free min(d2) + max(b^2*d2) ==============
    float dmin_[2][2], wloc[2][2];
    #pragma unroll
    for (int j = 0; j < 2; j++)
        #pragma unroll
        for (int p_ = 0; p_ < 2; p_++) { dmin_[j][p_] = 1e19f; wloc[j][p_] = 0.f; }

    const int lc0 = wn * 16 + 2 * ac;      // local belong col base
    #pragma unroll
    for (int i = 0; i < 4; i++) {
        int lr0 = wm * 64 + i * 16 + ar;
        float zs0 = zsv[i][0], zs1 = zsv[i][1];
        float2 b00 = *(const float2*)(sbel + lr0 * BELP + lc0);
        float2 b10 = *(const float2*)(sbel + (lr0 + 8) * BELP + lc0);
        float2 b01 = *(const float2*)(sbel + lr0 * BELP + lc0 + 8);
        float2 b11 = *(const float2*)(sbel + (lr0 + 8) * BELP + lc0 + 8);
        #pragma unroll
        for (int j = 0; j < 2; j++) {
            float es0 = esv[j][0], es1 = esv[j][1];
            float d00 = (zs0 + es0) + acc[i][j][0];
            float d01 = (zs0 + es1) + acc[i][j][1];
            float d10 = (zs1 + es0) + acc[i][j][2];
            float d11 = (zs1 + es1) + acc[i][j][3];
            float2 b0 = (j == 0) ? b00 : b01;
            float2 b1 = (j == 0) ? b10 : b11;
            wloc[j][0] = fmaxf(wloc[j][0], fmaxf(b0.x * b0.x * d00, b1.x * b1.x * d10));
            wloc[j][1] = fmaxf(wloc[j][1], fmaxf(b0.y * b0.y * d01, b1.y * b1.y * d11));
            dmin_[j][0] = fminf(dmin_[j][0], fminf(d00, d10));
            dmin_[j][1] = fminf(dmin_[j][1], fminf(d01, d11));
        }
    }

    // butterfly min/max over ar-lanes -> column-uniform dm, wmax
    float dm_[2][2], vm_[2][2], dthr_[2][2];
    #pragma unroll
    for (int j = 0; j < 2; j++)
        #pragma unroll
        for (int p_ = 0; p_ < 2; p_++) {
            float dm = dmin_[j][p_];
            #pragma unroll
            for (int off = 4; off < 32; off <<= 1)
                dm = fminf(dm, __shfl_xor_sync(0xffffffffu, dm, off));
            float wv = wloc[j][p_];
            #pragma unroll
            for (int off = 4; off < 32; off <<= 1)
                wv = fmaxf(wv, __shfl_xor_sync(0xffffffffu, wv, off));
            wloc[j][p_] = wv;
            dm_[j][p_] = dm;
            float vm = vfun(dm, fast, pf);
            vm_[j][p_] = vm;
            float vlim = vm + margin;
            dthr_[j][p_] = fast ? sqrtf(fmaxf(vlim, 0.f)) : __powf(vlim, 1.f / pf);
        }

    // =================== pass B: rare-window exp sums ===========================
    float s_[2][2] = {{0.f, 0.f}, {0.f, 0.f}};
    #pragma unroll
    for (int i = 0; i < 4; i++) {
        float zs0 = zsv[i][0], zs1 = zsv[i][1];
        #pragma unroll
        for (int j = 0; j < 2; j++) {
            float es0 = esv[j][0], es1 = esv[j][1];
            float dv[4];
            dv[0] = (zs0 + es0) + acc[i][j][0];
            dv[1] = (zs0 + es1) + acc[i][j][1];
            dv[2] = (zs1 + es0) + acc[i][j][2];
            dv[3] = (zs1 + es1) + acc[i][j][3];
            #pragma unroll
            for (int r = 0; r < 4; r++) {
                int p_ = r & 1;
                float d2 = dv[r];
                if (__builtin_expect(d2 < dthr_[j][p_], 0))
                    s_[j][p_] += __expf(alpha * (vfun(d2, fast, pf) - vm_[j][p_]));
            }
        }
    }

    float* sMD = (float*)(smraw + SM_MRG);
    float* sMS = sMD + 256;
    float* sMW = sMD + 512;
    #pragma unroll
    for (int j = 0; j < 2; j++)
        #pragma unroll
        for (int p_ = 0; p_ < 2; p_++) {
            float sv = s_[j][p_];
            #pragma unroll
            for (int off = 4; off < 32; off <<= 1)
                sv += __shfl_xor_sync(0xffffffffu, sv, off);
            if (lane < 4) {
                int col = wn * 16 + j * 8 + 2 * lane + p_;
                sMD[wm * 128 + col] = dm_[j][p_];
                sMS[wm * 128 + col] = sv;
                sMW[wm * 128 + col] = wloc[j][p_];
            }
        }
    __syncthreads();

    if (tid < 128) {
        int col = tid;
        float d0 = sMD[col], d1 = sMD[128 + col];
        float dm = fminf(d0, d1);
        float vm = vfun(dm, fast, pf);
        float s = sMS[col] * __expf(alpha * (vfun(d0, fast, pf) - vm))
                + sMS[128 + col] * __expf(alpha * (vfun(d1, fast, pf) - vm));
        g_pmin[ntile * M_TOT + m0 + col] = dm;
        g_psum[ntile * M_TOT + m0 + col] = s;
        atomicMax(&g_wmax[m0 + col],
                  __float_as_uint(fmaxf(sMW[col], sMW[128 + col])));
    }
}

// ---------------- kernel 3 (fused tail): newmax + lse + fixup + loss ----------
// grid 128 blocks x 256 threads. Each block: EMA newmax + combine 128 tiles ->
// lse + flag for its 32 columns. The LAST block (atomic ticket) then exactly
// recomputes flagged columns (rare; usually zero) and reduces lse -> loss.
__global__ void finalize_fused(const float* __restrict__ maxd,
                               const float* __restrict__ lsig,
                               const int* __restrict__ pptr, int has_p,
                               const float* __restrict__ z,
                               const float* __restrict__ e,
                               float* __restrict__ out) {
    __shared__ float s_t2[32];
    __shared__ float sdm[8][32];
    __shared__ float ssm[8][32];
    __shared__ int   s_last;
    const int lane = threadIdx.x & 31;
    const int warp = threadIdx.x >> 5;
    const int tid = threadIdx.x;
    const int col = blockIdx.x * 32 + lane;

    float alpha, pf; bool fast;
    get_alpha_p(lsig, pptr, has_p, alpha, pf, fast);

    if (tid < 32) {   // EMA new_max for this block's 32 columns
        float bm = sqrtf(__uint_as_float(g_wmax[col]));
        float nm = fmaxf(0.999f * maxd[col] + 0.001f * bm, 1e-8f);
        g_t[col] = nm;
        g_t2[col] = nm * nm;
        s_t2[lane] = nm * nm;
    }

    float dmc = 3.0e38f, s = 0.f;
    #pragma unroll 4
    for (int t = warp * 16; t < warp * 16 + 16; t++) {
        float pm = g_pmin[t * M_TOT + col];
        float ps = g_psum[t * M_TOT + col];
        if (pm < dmc) {
            s = s * __expf(alpha * (vfun(dmc, fast, pf) - vfun(pm, fast, pf))) + ps;
            dmc = pm;
        } else {
            s += ps * __expf(alpha * (vfun(pm, fast, pf) - vfun(dmc, fast, pf)));
        }
    }
    sdm[warp][lane] = dmc;
    ssm[warp][lane] = s;
    __syncthreads();

    if (warp == 0) {
        float dall = 3.0e38f;
        #pragma unroll
        for (int w = 0; w < 8; w++) dall = fminf(dall, sdm[w][lane]);
        float vall = vfun(dall, fast, pf);
        float sall = 0.f;
        #pragma unroll
        for (int w = 0; w < 8; w++)
            sall += ssm[w][lane] * __expf(alpha * (vfun(sdm[w][lane], fast, pf) - vall));
        g_lse[col] = alpha * vall + logf(sall);
        if (dall < s_t2[lane]) {         // some element takes the below branch
            int idx = atomicAdd(&g_flagcnt, 1);
            g_flags[idx] = col;
        }
    }

    // ---- last-block ticket (threadFenceReduction pattern) ----
    __threadfence();                     // each thread publishes its writes
    __syncthreads();
    if (tid == 0) {
        int t = atomicAdd(&g_done, 1);
        s_last = (t == gridDim.x - 1);
    }
    __syncthreads();
    if (!s_last) return;
    __threadfence();                     // acquire: other blocks' lse/t/flags

    // ---- fixup: exact recompute for flagged columns (usually none) ----
    {
        __shared__ float esm[64];
        __shared__ float red_v[256];
        __shared__ float red_s[256];
        const int cnt = g_flagcnt;
        const float elo = 2.f / pf, ehi = 2.f * pf;
        for (int f = 0; f < cnt; f++) {
            int fcol = g_flags[f];
            if (tid < 64) esm[tid] = e[fcol * 64 + tid];
            __syncthreads();
            float t = g_t[fcol];
            float esq = g_esq[fcol];
            float vmin = 3.0e38f, sx = 0.f;
            for (int n = tid; n < N_TOT; n += 256) {
                const float* zp = z + (size_t)(n >> 10) * 65536 + (n & 1023);
                float dot = 0.f;
                #pragma unroll
                for (int k = 0; k < 64; k++) dot += zp[k * 1024] * esm[k];
                float d2 = fmaxf(g_zsq[n] + esq - 2.f * dot, 0.f);
                float dist = sqrtf(d2);
                float v;
                if (fast) v = (dist < t) ? dist : d2 * d2;
                else      v = (dist < t) ? __powf(dist, elo) : __powf(dist, ehi);
                if (v < vmin) {
                    sx = sx * __expf(alpha * (vmin - v)) + 1.f;
                    vmin = v;
                } else {
                    float a1 = alpha * (v - vmin);
                    if (a1 > -30.f) sx += __expf(a1);
                }
            }
            red_v[tid] = vmin; red_s[tid] = sx;
            __syncthreads();
            if (tid == 0) {
                float vm = 3.0e38f;
                for (int i = 0; i < 256; i++) vm = fminf(vm, red_v[i]);
                float ss = 0.f;
                for (int i = 0; i < 256; i++)
                    ss += red_s[i] * __expf(alpha * (red_v[i] - vm));
                g_lse[fcol] = alpha * vm + logf(ss);
            }
            __syncthreads();
        }
    }

    // ---- final reduction: loss = -mean(lse) + z_dim * log_sigma ----
    {
        __shared__ double red[256];
        double a = 0.0;
        for (int i = tid; i < M_TOT; i += 256) a += (double)g_lse[i];
        red[tid] = a;
        __syncthreads();
        for (int st = 128; st > 0; st >>= 1) {
            if (tid < st) red[tid] += red[tid + st];
            __syncthreads();
        }
        if (tid == 0) {
            double ls = (double)lsig[0];
            out[0] = (float)(-(red[0] / (double)M_TOT) + (double)KDIM * ls);
        }
    }
}

// ---------------- launch ----------------
extern "C" void kernel_launch(void* const* d_in, const int* in_sizes, int n_in,
                              void* d_out, int out_size) {
    const float* z      = (const float*)d_in[0];
    const float* e      = (const float*)d_in[1];
    const float* belong = (const float*)d_in[2];
    const float* lsig   = (const float*)d_in[3];
    const float* maxd   = (const float*)d_in[4];
    const int*   pptr   = (n_in > 5) ? (const int*)d_in[5] : nullptr;
    (void)in_sizes; (void)out_size;
    int has_p = pptr ? 1 : 0;

    cudaFuncSetAttribute(gemm_fused, cudaFuncAttributeMaxDynamicSharedMemorySize,
                         SMEM_BYTES);   // host-side API, idempotent (R10-proven)

    prep_all<<<N_TOT / 32, 256>>>(z, e);             // launch 1 (8x parallel prep)
    gemm_fused<<<dim3(MTILES, NTILES), 512, SMEM_BYTES>>>(z, e, belong, lsig,
                                                          pptr, has_p);  // launch 2
    finalize_fused<<<M_TOT / 32, 256>>>(maxd, lsig, pptr, has_p,
                                        z, e, (float*)d_out);            // launch 3
}